// round 6
// baseline (speedup 1.0000x reference)
#include <cuda_runtime.h>
#include <cuda_fp16.h>
#include <math.h>

#define N_ROWS   524288
#define W        101
#define LAMBDA_1 0.2
#define LAMBDA_2 0.05
#define EPS_F    1e-3f
#define C0_F     6.907755279e-3f          // -EPS * ln(EPS)

#define TILE     128                      // rows per block == threads per block
#define THREADS  128
#define SROW     104                      // fp16 elements per smem row (13 x 8)
#define NBLOCKS  (N_ROWS / TILE)          // 4096 exact

__device__ double   g_sum[3];
__device__ unsigned g_ticket;

__device__ __forceinline__ float warp_sum_f(float v) {
    #pragma unroll
    for (int o = 16; o; o >>= 1) v += __shfl_xor_sync(0xffffffffu, v, o);
    return v;
}
__device__ __forceinline__ unsigned warp_redux_add_u32(unsigned v) {
    unsigned r;
    asm volatile("redux.sync.add.u32 %0, %1, 0xffffffff;" : "=r"(r) : "r"(v));
    return r;
}

__global__ void __launch_bounds__(THREADS, 8)
mrl_kernel(const float* __restrict__ inp, const int* __restrict__ tgt,
           float* __restrict__ out) {
    __shared__ __half  sm[TILE * SROW];   // 26,624 B: e-values (fp16)
    __shared__ double  sb[(THREADS / 32) * 3];

    const int tid  = threadIdx.x;
    const int lane = tid & 31;
    const int warp = tid >> 5;
    const int row0 = blockIdx.x * TILE;

    // ---- staging: coalesced global read, exp, fp16 store (one row per warp) ----
    for (int r = warp; r < TILE; r += THREADS / 32) {
        const float* x = inp + (size_t)(row0 + r) * W;
        __half* srow = sm + r * SROW;
        float e0 = __expf(x[lane]);
        float e1 = __expf(x[lane + 32]);
        float e2 = __expf(x[lane + 64]);
        srow[lane]      = __float2half(e0);
        srow[lane + 32] = __float2half(e1);
        srow[lane + 64] = __float2half(e2);
        float e3 = 0.f;
        if (lane < W - 96) e3 = __expf(x[lane + 96]);     // lanes 0..4
        if (lane < SROW - 96) srow[lane + 96] = __float2half(e3); // lanes 0..7 (5..7 = pad zeros)
    }
    __syncthreads();

    // ---- per-thread row: pass 1 (denominator + age-weighted numerator) ----
    const int r = tid;
    const uint4* xv = (const uint4*)(sm + r * SROW);      // 16B-aligned (208B row stride)

    float s0 = 0.f, s1 = 0.f, w0 = 0.f, w1 = 0.f;
    #pragma unroll
    for (int i = 0; i < 13; i++) {
        uint4 u = xv[i];
        float2 f0 = __half22float2(*reinterpret_cast<const __half2*>(&u.x));
        float2 f1 = __half22float2(*reinterpret_cast<const __half2*>(&u.y));
        float2 f2 = __half22float2(*reinterpret_cast<const __half2*>(&u.z));
        float2 f3 = __half22float2(*reinterpret_cast<const __half2*>(&u.w));
        const float j = (float)(8 * i);
        s0 += f0.x + f0.y;  w0 = fmaf(j + 0.f, f0.x, fmaf(j + 1.f, f0.y, w0));
        s1 += f1.x + f1.y;  w1 = fmaf(j + 2.f, f1.x, fmaf(j + 3.f, f1.y, w1));
        s0 += f2.x + f2.y;  w0 = fmaf(j + 4.f, f2.x, fmaf(j + 5.f, f2.y, w0));
        s1 += f3.x + f3.y;  w1 = fmaf(j + 6.f, f3.x, fmaf(j + 7.f, f3.y, w1));
    }
    const float inv  = __fdividef(1.f, s0 + s1);
    const int   t    = tgt[row0 + r];
    const float pg   = __half2float(sm[r * SROW + t]) * inv;
    const float mean = (w0 + w1) * inv;

    // ---- pass 2: residue + K (branchless). Pad bins (e=0 -> q=EPS) each add
    // exactly C0, pre-subtracted via the -3*C0 init. ----
    float    rA = -3.f * C0_F, rB = 0.f;
    unsigned k  = 0u;
    #pragma unroll
    for (int i = 0; i < 13; i++) {
        uint4 u = xv[i];
        float2 f0 = __half22float2(*reinterpret_cast<const __half2*>(&u.x));
        float2 f1 = __half22float2(*reinterpret_cast<const __half2*>(&u.y));
        float2 f2 = __half22float2(*reinterpret_cast<const __half2*>(&u.z));
        float2 f3 = __half22float2(*reinterpret_cast<const __half2*>(&u.w));
        float e[8] = {f0.x, f0.y, f1.x, f1.y, f2.x, f2.y, f3.x, f3.y};
        #pragma unroll
        for (int m = 0; m < 8; m++) {
            float p  = e[m] * inv;
            float q  = p + EPS_F;
            float lq = __logf(q);
            bool below = (p < pg);
            ((m & 1) ? rB : rA) += below ? (-q * lq) : C0_F;
            k += below ? 0u : 1u;
        }
    }

    float d    = mean - (float)t;
    float accM = d * d;
    float accR = rA + rB;

    // ---- block + grid reduction ----
    accM = warp_sum_f(accM);
    accR = warp_sum_f(accR);
    unsigned accK = warp_redux_add_u32(k);

    if (lane == 0) {
        sb[warp * 3 + 0] = (double)accM;
        sb[warp * 3 + 1] = (double)accR;
        sb[warp * 3 + 2] = (double)accK;
    }
    __syncthreads();

    if (tid == 0) {
        double tM = 0.0, tR = 0.0, tK = 0.0;
        #pragma unroll
        for (int i = 0; i < THREADS / 32; i++) {
            tM += sb[i * 3 + 0];
            tR += sb[i * 3 + 1];
            tK += sb[i * 3 + 2];
        }
        atomicAdd(&g_sum[0], tM);
        atomicAdd(&g_sum[1], tR);
        atomicAdd(&g_sum[2], tK);
        __threadfence();
        unsigned old = atomicAdd(&g_ticket, 1u);
        if (old == (unsigned)(gridDim.x - 1)) {
            volatile double* gs = g_sum;
            double m  = gs[0];
            double rr = gs[1];
            double kk = gs[2];
            const double invN = 1.0 / (double)N_ROWS;
            out[0] = (float)(LAMBDA_1 * 0.5 * m * invN);
            out[1] = (float)(LAMBDA_2 * rr * invN);
            out[2] = (float)(kk * invN);
            gs[0] = 0.0; gs[1] = 0.0; gs[2] = 0.0;
            __threadfence();
            g_ticket = 0u;
        }
    }
}

extern "C" void kernel_launch(void* const* d_in, const int* in_sizes, int n_in,
                              void* d_out, int out_size) {
    const float* inp = (const float*)d_in[0];
    const int*   tgt = (const int*)d_in[1];
    float*       out = (float*)d_out;
    (void)in_sizes; (void)n_in; (void)out_size;

    mrl_kernel<<<NBLOCKS, THREADS>>>(inp, tgt, out);
}

// round 8
// speedup vs baseline: 1.4516x; 1.4516x over previous
#include <cuda_runtime.h>
#include <math.h>

#define N_ROWS   524288
#define W        101
#define LAMBDA_1 0.2
#define LAMBDA_2 0.05
#define EPS_F    1e-3f

#define TILE     64                        // rows per smem tile
#define THREADS  512                       // 8 threads per row
#define SROW     104                       // fp32 words per smem row (pad 3)
#define NTILES   (N_ROWS / TILE)           // 8192
#define GRID     296                       // 2 blocks per SM, persistent

// exact constants used only in the scalar finalize (double)
#define D_LN2    0.6931471805599453
#define D_C0     6.907755278982137e-3      // -eps*ln(eps)
#define D_EPSLG2 (-9.965784284662087e-3)   // eps*log2(eps)

__device__ double   g_sum[3];              // [0]=sum d^2, [1]=sum q*lg2(q) (raw), [2]=sum K
__device__ unsigned g_ticket;

__device__ __forceinline__ unsigned warp_redux_add_u32(unsigned v) {
    unsigned r;
    asm volatile("redux.sync.add.u32 %0, %1, 0xffffffff;" : "=r"(r) : "r"(v));
    return r;
}

__global__ void __launch_bounds__(THREADS, 2)
mrl_kernel(const float* __restrict__ inp, const int* __restrict__ tgt,
           float* __restrict__ out) {
    __shared__ float  sm[TILE * SROW];     // 26,624 B
    __shared__ double sb[(THREADS / 32) * 3];

    const int tid  = threadIdx.x;
    const int lane = tid & 31;
    const int warp = tid >> 5;
    const int sub  = tid & 7;              // position within 8-thread row group
    const int rloc = tid >> 3;             // row within tile, 0..63
    const int base = 13 * sub;             // first bin owned by this thread

    float    accM = 0.f;                   // sum of (mean - t)^2   (sub==0 lanes only)
    float    accQ = 0.f;                   // sum of q*log2(q) over below-bins (incl pads)
    unsigned accK = 0u;                    // count of not-below bins

    for (int tile = blockIdx.x; tile < NTILES; tile += GRID) {
        const int row0 = tile * TILE;

        // ---- stage 64 rows: warp-per-row, 4 unrolled rows per warp ----
        #pragma unroll
        for (int i = 0; i < 4; i++) {
            const int r = warp + 16 * i;
            const float* x = inp + (size_t)(row0 + r) * W;
            float* s = sm + r * SROW;
            float a = x[lane];
            float b = x[lane + 32];
            float c = x[lane + 64];
            s[lane]      = a;
            s[lane + 32] = b;
            s[lane + 64] = c;
            if (lane < 8)                  // pads (101..103) hold -1000 -> e = 0
                s[lane + 96] = (lane < 5) ? x[lane + 96] : -1000.f;
        }
        __syncthreads();

        // ---- pass 1: e_j into registers; local (s, sum i*e) ----
        const float* xr = sm + rloc * SROW + base;   // conflict-free: 8*rloc+13*sub mod 32
        float e[13];
        float s = 0.f, m1 = 0.f;
        #pragma unroll
        for (int i = 0; i < 13; i++) {
            float ev = __expf(xr[i]);
            e[i] = ev;
            s  += ev;
            m1  = fmaf((float)i, ev, m1);
        }
        float wn = fmaf((float)base, s, m1);

        // reduce (s, wn) over the 8-lane row group
        #pragma unroll
        for (int o = 1; o < 8; o <<= 1) {
            s  += __shfl_xor_sync(0xffffffffu, s,  o);
            wn += __shfl_xor_sync(0xffffffffu, wn, o);
        }

        const int   t   = tgt[row0 + rloc];
        const float et  = __expf(sm[rloc * SROW + t]);   // bit-identical to owner's e_t
        const float inv = __fdividef(1.f, s);

        if (sub == 0) {
            float d = fmaf(wn, inv, -(float)t);
            accM = fmaf(d, d, accM);
        }

        // ---- pass 2: register-resident residue + K ----
        #pragma unroll
        for (int i = 0; i < 13; i++) {
            float q  = fmaf(e[i], inv, EPS_F);
            float lq = __log2f(q);
            bool below = (e[i] < et);                    // == (p < pg)
            accQ = below ? fmaf(q, lq, accQ) : accQ;
            accK += below ? 0u : 1u;
        }
        __syncthreads();                    // smem reuse guard for next tile
    }

    // ---- block reduction ----
    #pragma unroll
    for (int o = 16; o; o >>= 1) {
        accM += __shfl_xor_sync(0xffffffffu, accM, o);
        accQ += __shfl_xor_sync(0xffffffffu, accQ, o);
    }
    accK = warp_redux_add_u32(accK);

    if (lane == 0) {
        sb[warp * 3 + 0] = (double)accM;
        sb[warp * 3 + 1] = (double)accQ;
        sb[warp * 3 + 2] = (double)accK;
    }
    __syncthreads();

    if (tid == 0) {
        double tM = 0.0, tQ = 0.0, tK = 0.0;
        #pragma unroll
        for (int i = 0; i < THREADS / 32; i++) {
            tM += sb[i * 3 + 0];
            tQ += sb[i * 3 + 1];
            tK += sb[i * 3 + 2];
        }
        atomicAdd(&g_sum[0], tM);
        atomicAdd(&g_sum[1], tQ);
        atomicAdd(&g_sum[2], tK);
        __threadfence();
        unsigned old = atomicAdd(&g_ticket, 1u);
        if (old == (unsigned)(GRID - 1)) {
            volatile double* gs = g_sum;
            double M = gs[0];
            double Q = gs[1];
            double K = gs[2];
            // remove the 3 pad bins per row (each contributed eps*lg2(eps) to Q)
            double Qadj = Q - 3.0 * (double)N_ROWS * D_EPSLG2;
            double residue_sum = -D_LN2 * Qadj + D_C0 * K;
            const double invN = 1.0 / (double)N_ROWS;
            out[0] = (float)(LAMBDA_1 * 0.5 * M * invN);
            out[1] = (float)(LAMBDA_2 * residue_sum * invN);
            out[2] = (float)(K * invN);
            gs[0] = 0.0; gs[1] = 0.0; gs[2] = 0.0;
            __threadfence();
            g_ticket = 0u;
        }
    }
}

extern "C" void kernel_launch(void* const* d_in, const int* in_sizes, int n_in,
                              void* d_out, int out_size) {
    const float* inp = (const float*)d_in[0];
    const int*   tgt = (const int*)d_in[1];
    float*       out = (float*)d_out;
    (void)in_sizes; (void)n_in; (void)out_size;

    mrl_kernel<<<GRID, THREADS>>>(inp, tgt, out);
}

// round 13
// speedup vs baseline: 2.4720x; 1.7030x over previous
#include <cuda_runtime.h>
#include <cstdint>
#include <math.h>

#define N_ROWS   524288
#define W        101
#define LAMBDA_1 0.2
#define LAMBDA_2 0.05
#define EPS_F    1e-3f

#define TILE     32                        // rows per smem buffer
#define THREADS  256                       // 8 threads per row
#define SROW     104                       // fp32 words per smem row (3 pad)
#define NTILES   (N_ROWS / TILE)           // 16384
#define GRID     888                       // 6 blocks per SM, persistent

// exact constants for the scalar finalize (double)
#define D_LN2    0.6931471805599453
#define D_C0     6.907755278982137e-3      // -eps*ln(eps)
#define D_EPSLG2 (-9.965784284662087e-3)   // eps*log2(eps)

__device__ double   g_sum[3];              // [0]=sum d^2, [1]=raw sum q*lg2 q, [2]=sum K
__device__ unsigned g_ticket;

__device__ __forceinline__ unsigned warp_redux_add_u32(unsigned v) {
    unsigned r;
    asm volatile("redux.sync.add.u32 %0, %1, 0xffffffff;" : "=r"(r) : "r"(v));
    return r;
}
__device__ __forceinline__ unsigned int smem_u32(const void* p) {
    unsigned int a;
    asm("{ .reg .u64 t; cvta.to.shared.u64 t, %1; cvt.u32.u64 %0, t; }" : "=r"(a) : "l"(p));
    return a;
}
__device__ __forceinline__ void cp4(unsigned int dst, const float* src) {
    asm volatile("cp.async.ca.shared.global [%0], [%1], 4;" :: "r"(dst), "l"(src));
}
__device__ __forceinline__ void cp_commit() { asm volatile("cp.async.commit_group;"); }
__device__ __forceinline__ void cp_wait1()  { asm volatile("cp.async.wait_group 1;"); }

// warp w stages rows 4w..4w+3 of one tile via 4B cp.async (coalesced per row)
__device__ __forceinline__ void stage_tile(unsigned int sbuf, const float* gbase,
                                           int lane, int warp) {
    #pragma unroll
    for (int i = 0; i < 4; i++) {
        const int r = warp * 4 + i;
        const float* g = gbase + (size_t)r * W;
        const unsigned int s = sbuf + (unsigned int)(r * SROW) * 4u;
        cp4(s + (unsigned int)lane * 4u,        g + lane);
        cp4(s + (unsigned int)(lane + 32) * 4u, g + lane + 32);
        cp4(s + (unsigned int)(lane + 64) * 4u, g + lane + 64);
        if (lane < 5)
            cp4(s + (unsigned int)(lane + 96) * 4u, g + lane + 96);
    }
}

__global__ void __launch_bounds__(THREADS, 6)
mrl_kernel(const float* __restrict__ inp, const int* __restrict__ tgt,
           float* __restrict__ out) {
    __shared__ float  sm[2][TILE * SROW];  // 2 x 13,312 B
    __shared__ double sb[(THREADS / 32) * 3];

    const int tid  = threadIdx.x;
    const int lane = tid & 31;
    const int warp = tid >> 5;
    const int sub  = tid & 7;              // slot within 8-thread row group
    const int rloc = tid >> 3;             // row within tile, 0..31
    const int base = 13 * sub;             // first bin owned (bins 101..103 = pads)

    const unsigned int sbuf0 = smem_u32(&sm[0][0]);
    const unsigned int sbuf1 = smem_u32(&sm[1][0]);

    // pad columns 101..103 of every row, both buffers (never overwritten)
    if (tid < TILE) {
        #pragma unroll
        for (int b = 0; b < 2; b++) {
            sm[b][tid * SROW + 101] = -1000.f;
            sm[b][tid * SROW + 102] = -1000.f;
            sm[b][tid * SROW + 103] = -1000.f;
        }
    }

    // pipeline prologue: stage first tile, prefetch its target
    const int tile0 = blockIdx.x;
    int tcur = 0;
    if (tile0 < NTILES) {
        stage_tile(sbuf0, inp + (size_t)tile0 * TILE * W, lane, warp);
        tcur = tgt[tile0 * TILE + rloc];
    }
    cp_commit();

    float    accM = 0.f, accQ = 0.f;
    unsigned accK = 0u;
    int cur = 0;

    for (int tile = tile0; tile < NTILES; tile += GRID) {
        // stage next tile into the other buffer; prefetch its target
        const int nxt = tile + GRID;
        int tnext = 0;
        if (nxt < NTILES) {
            stage_tile(cur ? sbuf0 : sbuf1, inp + (size_t)nxt * TILE * W, lane, warp);
            tnext = tgt[nxt * TILE + rloc];
        }
        cp_commit();
        cp_wait1();                        // current tile's group complete
        __syncthreads();                   // visible to all warps

        // ---- pass 1: e into registers; (s, wn) over the row ----
        const float* xr = &sm[cur][rloc * SROW + base];   // conflict-free
        float e[13];
        float s = 0.f, m1 = 0.f;
        #pragma unroll
        for (int i = 0; i < 13; i++) {
            float ev = __expf(xr[i]);
            e[i] = ev;
            s  += ev;
            m1  = fmaf((float)i, ev, m1);
        }
        float wn = fmaf((float)base, s, m1);
        #pragma unroll
        for (int o = 1; o < 8; o <<= 1) {
            s  += __shfl_xor_sync(0xffffffffu, s,  o);
            wn += __shfl_xor_sync(0xffffffffu, wn, o);
        }

        const int   t   = tcur;
        const float et  = __expf(sm[cur][rloc * SROW + t]);
        const float inv = __fdividef(1.f, s);

        if (sub == 0) {
            float d = fmaf(wn, inv, -(float)t);
            accM = fmaf(d, d, accM);
        }

        // ---- pass 2: register-resident residue + K ----
        #pragma unroll
        for (int i = 0; i < 13; i++) {
            float q  = fmaf(e[i], inv, EPS_F);
            float lq = __log2f(q);
            bool below = (e[i] < et);      // == (p < pg)
            accQ = below ? fmaf(q, lq, accQ) : accQ;
            accK += below ? 0u : 1u;
        }
        __syncthreads();                   // all warps done reading buf[cur]
        tcur = tnext;
        cur ^= 1;
    }

    // ---- block + grid reduction ----
    #pragma unroll
    for (int o = 16; o; o >>= 1) {
        accM += __shfl_xor_sync(0xffffffffu, accM, o);
        accQ += __shfl_xor_sync(0xffffffffu, accQ, o);
    }
    accK = warp_redux_add_u32(accK);

    if (lane == 0) {
        sb[warp * 3 + 0] = (double)accM;
        sb[warp * 3 + 1] = (double)accQ;
        sb[warp * 3 + 2] = (double)accK;
    }
    __syncthreads();

    if (tid == 0) {
        double tM = 0.0, tQ = 0.0, tK = 0.0;
        #pragma unroll
        for (int i = 0; i < THREADS / 32; i++) {
            tM += sb[i * 3 + 0];
            tQ += sb[i * 3 + 1];
            tK += sb[i * 3 + 2];
        }
        atomicAdd(&g_sum[0], tM);
        atomicAdd(&g_sum[1], tQ);
        atomicAdd(&g_sum[2], tK);
        __threadfence();
        unsigned old = atomicAdd(&g_ticket, 1u);
        if (old == (unsigned)(GRID - 1)) {
            volatile double* gs = g_sum;
            double M = gs[0];
            double Q = gs[1];
            double K = gs[2];
            // remove 3 pad bins per row (each contributed eps*lg2(eps) to Q)
            double Qadj = Q - 3.0 * (double)N_ROWS * D_EPSLG2;
            double residue_sum = -D_LN2 * Qadj + D_C0 * K;
            const double invN = 1.0 / (double)N_ROWS;
            out[0] = (float)(LAMBDA_1 * 0.5 * M * invN);
            out[1] = (float)(LAMBDA_2 * residue_sum * invN);
            out[2] = (float)(K * invN);
            gs[0] = 0.0; gs[1] = 0.0; gs[2] = 0.0;
            __threadfence();
            g_ticket = 0u;
        }
    }
}

extern "C" void kernel_launch(void* const* d_in, const int* in_sizes, int n_in,
                              void* d_out, int out_size) {
    const float* inp = (const float*)d_in[0];
    const int*   tgt = (const int*)d_in[1];
    float*       out = (float*)d_out;
    (void)in_sizes; (void)n_in; (void)out_size;

    mrl_kernel<<<GRID, THREADS>>>(inp, tgt, out);
}

// round 14
// speedup vs baseline: 2.5432x; 1.0288x over previous
#include <cuda_runtime.h>
#include <cstdint>
#include <math.h>

#define N_ROWS   524288
#define W        101
#define LAMBDA_1 0.2
#define LAMBDA_2 0.05
#define EPS_F    1e-3f

#define TILE     32                        // rows per smem buffer
#define THREADS  256                       // 8 threads per row
#define SROW     104                       // fp32 words per smem row (3 pad)
#define NTILES   (N_ROWS / TILE)           // 16384
#define GRID     888                       // 6 blocks per SM, persistent

// exact constants for the scalar finalize (double)
#define D_LN2    0.6931471805599453
#define D_C0     6.907755278982137e-3      // -eps*ln(eps)
#define D_EPSLG2 (-9.965784284662087e-3)   // eps*log2(eps)

__device__ double   g_sum[3];              // [0]=sum d^2, [1]=raw sum q*lg2 q, [2]=sum K
__device__ unsigned g_ticket;

__device__ __forceinline__ unsigned warp_redux_add_u32(unsigned v) {
    unsigned r;
    asm volatile("redux.sync.add.u32 %0, %1, 0xffffffff;" : "=r"(r) : "r"(v));
    return r;
}
__device__ __forceinline__ unsigned int smem_u32(const void* p) {
    unsigned int a;
    asm("{ .reg .u64 t; cvta.to.shared.u64 t, %1; cvt.u32.u64 %0, t; }" : "=r"(a) : "l"(p));
    return a;
}
// cp.async with compile-time byte offset folded into the instruction (no per-copy IADD)
#define CP4_OFF(dst, src, off) \
    asm volatile("cp.async.ca.shared.global [%0+" #off "], [%1+" #off "], 4;" \
                 :: "r"(dst), "l"(src))
__device__ __forceinline__ void cp_commit() { asm volatile("cp.async.commit_group;"); }
__device__ __forceinline__ void cp_wait1()  { asm volatile("cp.async.wait_group 1;"); }

// warp w stages rows 4w..4w+3 of one tile; 1 address setup per row, imm offsets
__device__ __forceinline__ void stage_tile(unsigned int sbuf, const float* gbase,
                                           int lane, int warp) {
    #pragma unroll
    for (int i = 0; i < 4; i++) {
        const int r = warp * 4 + i;
        const float*       g = gbase + (size_t)r * W + lane;
        const unsigned int s = sbuf + (unsigned int)(r * SROW + lane) * 4u;
        CP4_OFF(s, g, 0);
        CP4_OFF(s, g, 128);
        CP4_OFF(s, g, 256);
        if (lane < 5) CP4_OFF(s, g, 384);
    }
}

__global__ void __launch_bounds__(THREADS, 6)
mrl_kernel(const float* __restrict__ inp, const int* __restrict__ tgt,
           float* __restrict__ out) {
    __shared__ float  sm[2][TILE * SROW];  // 2 x 13,312 B
    __shared__ double sb[(THREADS / 32) * 3];

    const int tid  = threadIdx.x;
    const int lane = tid & 31;
    const int warp = tid >> 5;
    const int sub  = tid & 7;              // slot within 8-thread row group
    const int rloc = tid >> 3;             // row within tile, 0..31
    const int c4   = 4 * sub;              // float4 chunk offset within row

    const unsigned int sbuf0 = smem_u32(&sm[0][0]);
    const unsigned int sbuf1 = smem_u32(&sm[1][0]);

    // pad columns 101..103 of every row, both buffers (never overwritten)
    if (tid < TILE) {
        #pragma unroll
        for (int b = 0; b < 2; b++) {
            sm[b][tid * SROW + 101] = -1000.f;
            sm[b][tid * SROW + 102] = -1000.f;
            sm[b][tid * SROW + 103] = -1000.f;
        }
    }

    // pipeline prologue: stage first tile, prefetch its target
    const int tile0 = blockIdx.x;
    int tcur = 0;
    if (tile0 < NTILES) {
        stage_tile(sbuf0, inp + (size_t)tile0 * TILE * W, lane, warp);
        tcur = tgt[tile0 * TILE + rloc];
    }
    cp_commit();

    float    accM = 0.f, accQa = 0.f, accQb = 0.f;
    unsigned accK = 0u;
    int cur = 0;

    // relative bin weights for the 12 vector bins (chunk bases 0/32/64 + k)
    const float WREL[12] = {0.f,1.f,2.f,3.f, 32.f,33.f,34.f,35.f, 64.f,65.f,66.f,67.f};

    for (int tile = tile0; tile < NTILES; tile += GRID) {
        // stage next tile into the other buffer; prefetch its target
        const int nxt = tile + GRID;
        int tnext = 0;
        if (nxt < NTILES) {
            stage_tile(cur ? sbuf0 : sbuf1, inp + (size_t)nxt * TILE * W, lane, warp);
            tnext = tgt[nxt * TILE + rloc];
        }
        cp_commit();
        cp_wait1();                        // current tile's group complete
        __syncthreads();                   // visible to all warps

        // ---- pass 1: vector loads, exp into registers, (s, wn) ----
        const float* xr = &sm[cur][rloc * SROW];
        float4 A = *reinterpret_cast<const float4*>(xr + c4);
        float4 B = *reinterpret_cast<const float4*>(xr + 32 + c4);
        float4 C = *reinterpret_cast<const float4*>(xr + 64 + c4);
        float  vD = xr[96 + sub];          // subs 5..7 hit pads (-1000 -> e=0)

        float e[13];
        e[0]  = __expf(A.x); e[1]  = __expf(A.y); e[2]  = __expf(A.z); e[3]  = __expf(A.w);
        e[4]  = __expf(B.x); e[5]  = __expf(B.y); e[6]  = __expf(B.z); e[7]  = __expf(B.w);
        e[8]  = __expf(C.x); e[9]  = __expf(C.y); e[10] = __expf(C.z); e[11] = __expf(C.w);
        e[12] = __expf(vD);

        float s = 0.f, m1 = 0.f;
        #pragma unroll
        for (int i = 0; i < 12; i++) {
            s  += e[i];
            m1  = fmaf(WREL[i], e[i], m1); // imm-multiplier FFMA
        }
        float wn = fmaf((float)c4, s, m1); // global base 4*sub over chunks A/B/C
        s  += e[12];
        wn  = fmaf((float)(96 + sub), e[12], wn);

        // reduce (s, wn) over the 8-thread row group
        #pragma unroll
        for (int o = 1; o < 8; o <<= 1) {
            s  += __shfl_xor_sync(0xffffffffu, s,  o);
            wn += __shfl_xor_sync(0xffffffffu, wn, o);
        }

        const int   t   = tcur;
        const float et  = __expf(sm[cur][rloc * SROW + t]);  // bit-identical to owner's e_t
        const float inv = __fdividef(1.f, s);

        if (sub == 0) {
            float d = fmaf(wn, inv, -(float)t);
            accM = fmaf(d, d, accM);
        }

        // ---- pass 2: register-resident residue + K (predicated) ----
        #pragma unroll
        for (int i = 0; i < 13; i++) {
            float q  = fmaf(e[i], inv, EPS_F);
            float lq = __log2f(q);
            if (e[i] < et) {               // == (p < pg); pads always below
                if (i & 1) accQb = fmaf(q, lq, accQb);
                else       accQa = fmaf(q, lq, accQa);
            } else {
                accK++;
            }
        }
        __syncthreads();                   // all warps done reading buf[cur]
        tcur = tnext;
        cur ^= 1;
    }

    float accQ = accQa + accQb;

    // ---- block + grid reduction ----
    #pragma unroll
    for (int o = 16; o; o >>= 1) {
        accM += __shfl_xor_sync(0xffffffffu, accM, o);
        accQ += __shfl_xor_sync(0xffffffffu, accQ, o);
    }
    accK = warp_redux_add_u32(accK);

    if (lane == 0) {
        sb[warp * 3 + 0] = (double)accM;
        sb[warp * 3 + 1] = (double)accQ;
        sb[warp * 3 + 2] = (double)accK;
    }
    __syncthreads();

    if (tid == 0) {
        double tM = 0.0, tQ = 0.0, tK = 0.0;
        #pragma unroll
        for (int i = 0; i < THREADS / 32; i++) {
            tM += sb[i * 3 + 0];
            tQ += sb[i * 3 + 1];
            tK += sb[i * 3 + 2];
        }
        atomicAdd(&g_sum[0], tM);
        atomicAdd(&g_sum[1], tQ);
        atomicAdd(&g_sum[2], tK);
        __threadfence();
        unsigned old = atomicAdd(&g_ticket, 1u);
        if (old == (unsigned)(GRID - 1)) {
            volatile double* gs = g_sum;
            double M = gs[0];
            double Q = gs[1];
            double K = gs[2];
            // remove 3 pad bins per row (each contributed eps*lg2(eps) to Q)
            double Qadj = Q - 3.0 * (double)N_ROWS * D_EPSLG2;
            double residue_sum = -D_LN2 * Qadj + D_C0 * K;
            const double invN = 1.0 / (double)N_ROWS;
            out[0] = (float)(LAMBDA_1 * 0.5 * M * invN);
            out[1] = (float)(LAMBDA_2 * residue_sum * invN);
            out[2] = (float)(K * invN);
            gs[0] = 0.0; gs[1] = 0.0; gs[2] = 0.0;
            __threadfence();
            g_ticket = 0u;
        }
    }
}

extern "C" void kernel_launch(void* const* d_in, const int* in_sizes, int n_in,
                              void* d_out, int out_size) {
    const float* inp = (const float*)d_in[0];
    const int*   tgt = (const int*)d_in[1];
    float*       out = (float*)d_out;
    (void)in_sizes; (void)n_in; (void)out_size;

    mrl_kernel<<<GRID, THREADS>>>(inp, tgt, out);
}

// round 16
// speedup vs baseline: 2.6595x; 1.0457x over previous
#include <cuda_runtime.h>
#include <cstdint>
#include <math.h>

#define N_ROWS   524288
#define W        101
#define LAMBDA_1 0.2
#define LAMBDA_2 0.05
#define EPS_F    1e-3f

#define TILE     32                        // rows per smem buffer
#define THREADS  256                       // 8 threads per row
#define SROW     104                       // fp32 words per smem row (3 pad)
#define NTILES   (N_ROWS / TILE)           // 16384
#define GRID     888                       // 6 blocks per SM, persistent

// exact constants for the scalar finalize (double)
#define D_LN2    0.6931471805599453
#define D_C0     6.907755278982137e-3      // -eps*ln(eps)
#define D_EPSLG2 (-9.965784284662087e-3)   // eps*log2(eps)

__device__ double   g_sum[3];              // [0]=sum d^2, [1]=raw sum q*lg2 q, [2]=sum K
__device__ unsigned g_ticket;

__device__ __forceinline__ unsigned warp_redux_add_u32(unsigned v) {
    unsigned r;
    asm volatile("redux.sync.add.u32 %0, %1, 0xffffffff;" : "=r"(r) : "r"(v));
    return r;
}
__device__ __forceinline__ unsigned int smem_u32(const void* p) {
    unsigned int a;
    asm("{ .reg .u64 t; cvta.to.shared.u64 t, %1; cvt.u32.u64 %0, t; }" : "=r"(a) : "l"(p));
    return a;
}
// cp.async with compile-time byte offset folded into the instruction
#define CP4_OFF(dst, src, off) \
    asm volatile("cp.async.ca.shared.global [%0+" #off "], [%1+" #off "], 4;" \
                 :: "r"(dst), "l"(src))
__device__ __forceinline__ void cp_commit() { asm volatile("cp.async.commit_group;"); }
__device__ __forceinline__ void cp_wait1()  { asm volatile("cp.async.wait_group 1;"); }

// warp w stages its OWN rows 4w..4w+3 of one tile; imm offsets, 1 addr setup/row
__device__ __forceinline__ void stage_tile(unsigned int sbuf, const float* gbase,
                                           int lane, int warp) {
    #pragma unroll
    for (int i = 0; i < 4; i++) {
        const int r = warp * 4 + i;
        const float*       g = gbase + (size_t)r * W + lane;
        const unsigned int s = sbuf + (unsigned int)(r * SROW + lane) * 4u;
        CP4_OFF(s, g, 0);
        CP4_OFF(s, g, 128);
        CP4_OFF(s, g, 256);
        if (lane < 5) CP4_OFF(s, g, 384);
    }
}

__global__ void __launch_bounds__(THREADS, 6)
mrl_kernel(const float* __restrict__ inp, const int* __restrict__ tgt,
           float* __restrict__ out) {
    __shared__ float  sm[2][TILE * SROW];  // 2 x 13,312 B
    __shared__ double sb[(THREADS / 32) * 3];

    const int tid  = threadIdx.x;
    const int lane = tid & 31;
    const int warp = tid >> 5;
    const int sub  = tid & 7;              // slot within 8-thread row group
    const int rloc = tid >> 3;             // row within tile = 4*warp + (lane>>3)
    const int c4   = 4 * sub;              // float4 chunk offset within row

    const unsigned int sbuf0 = smem_u32(&sm[0][0]);
    const unsigned int sbuf1 = smem_u32(&sm[1][0]);

    // pad columns 101..103 of every row, both buffers (never overwritten).
    if (tid < TILE) {
        #pragma unroll
        for (int b = 0; b < 2; b++) {
            sm[b][tid * SROW + 101] = -1000.f;
            sm[b][tid * SROW + 102] = -1000.f;
            sm[b][tid * SROW + 103] = -1000.f;
        }
    }
    __syncthreads();                       // one-time: pads visible to all warps

    // pipeline prologue: warp stages its rows of the first tile; prefetch target
    const int tile0 = blockIdx.x;
    int tcur = 0;
    if (tile0 < NTILES) {
        stage_tile(sbuf0, inp + (size_t)tile0 * TILE * W, lane, warp);
        tcur = tgt[tile0 * TILE + rloc];
    }
    cp_commit();

    float    accM = 0.f, accQa = 0.f, accQb = 0.f;
    unsigned accK = 0u;
    int cur = 0;

    // relative bin weights for the 12 vector bins (chunk bases 0/32/64 + k)
    const float WREL[12] = {0.f,1.f,2.f,3.f, 32.f,33.f,34.f,35.f, 64.f,65.f,66.f,67.f};

    for (int tile = tile0; tile < NTILES; tile += GRID) {
        // stage next tile (this warp's rows) into the other buffer
        const int nxt = tile + GRID;
        int tnext = 0;
        if (nxt < NTILES) {
            stage_tile(cur ? sbuf0 : sbuf1, inp + (size_t)nxt * TILE * W, lane, warp);
            tnext = tgt[nxt * TILE + rloc];
        }
        cp_commit();
        cp_wait1();                        // this lane's current-tile copies done
        __syncwarp();                      // -> whole warp's copies done (warp-local data)

        // ---- pass 1: vector loads, exp into registers, (s, wn) ----
        const float* xr = &sm[cur][rloc * SROW];
        float4 A = *reinterpret_cast<const float4*>(xr + c4);
        float4 B = *reinterpret_cast<const float4*>(xr + 32 + c4);
        float4 C = *reinterpret_cast<const float4*>(xr + 64 + c4);
        float  vD = xr[96 + sub];          // subs 5..7 hit pads (-1000 -> e=0)

        float e[13];
        e[0]  = __expf(A.x); e[1]  = __expf(A.y); e[2]  = __expf(A.z); e[3]  = __expf(A.w);
        e[4]  = __expf(B.x); e[5]  = __expf(B.y); e[6]  = __expf(B.z); e[7]  = __expf(B.w);
        e[8]  = __expf(C.x); e[9]  = __expf(C.y); e[10] = __expf(C.z); e[11] = __expf(C.w);
        e[12] = __expf(vD);

        float s = 0.f, m1 = 0.f;
        #pragma unroll
        for (int i = 0; i < 12; i++) {
            s  += e[i];
            m1  = fmaf(WREL[i], e[i], m1); // imm-multiplier FFMA
        }
        float wn = fmaf((float)c4, s, m1);
        s  += e[12];
        wn  = fmaf((float)(96 + sub), e[12], wn);

        // reduce (s, wn) over the 8-thread row group (within warp)
        #pragma unroll
        for (int o = 1; o < 8; o <<= 1) {
            s  += __shfl_xor_sync(0xffffffffu, s,  o);
            wn += __shfl_xor_sync(0xffffffffu, wn, o);
        }

        const int   t   = tcur;
        const float et  = __expf(sm[cur][rloc * SROW + t]);  // bit-identical to owner's e_t
        const float inv = __fdividef(1.f, s);

        if (sub == 0) {
            float d = fmaf(wn, inv, -(float)t);
            accM = fmaf(d, d, accM);
        }

        // ---- pass 2: register-resident residue + K (predicated) ----
        #pragma unroll
        for (int i = 0; i < 13; i++) {
            float q  = fmaf(e[i], inv, EPS_F);
            float lq = __log2f(q);
            if (e[i] < et) {               // == (p < pg); pads always below
                if (i & 1) accQb = fmaf(q, lq, accQb);
                else       accQa = fmaf(q, lq, accQa);
            } else {
                accK++;
            }
        }
        __syncwarp();                      // warp done reading buf[cur] before re-stage
        tcur = tnext;
        cur ^= 1;
    }

    float accQ = accQa + accQb;

    // ---- block + grid reduction ----
    #pragma unroll
    for (int o = 16; o; o >>= 1) {
        accM += __shfl_xor_sync(0xffffffffu, accM, o);
        accQ += __shfl_xor_sync(0xffffffffu, accQ, o);
    }
    accK = warp_redux_add_u32(accK);

    if (lane == 0) {
        sb[warp * 3 + 0] = (double)accM;
        sb[warp * 3 + 1] = (double)accQ;
        sb[warp * 3 + 2] = (double)accK;
    }
    __syncthreads();

    if (tid == 0) {
        double tM = 0.0, tQ = 0.0, tK = 0.0;
        #pragma unroll
        for (int i = 0; i < THREADS / 32; i++) {
            tM += sb[i * 3 + 0];
            tQ += sb[i * 3 + 1];
            tK += sb[i * 3 + 2];
        }
        atomicAdd(&g_sum[0], tM);
        atomicAdd(&g_sum[1], tQ);
        atomicAdd(&g_sum[2], tK);
        __threadfence();
        unsigned old = atomicAdd(&g_ticket, 1u);
        if (old == (unsigned)(GRID - 1)) {
            volatile double* gs = g_sum;
            double M = gs[0];
            double Q = gs[1];
            double K = gs[2];
            // remove 3 pad bins per row (each contributed eps*lg2(eps) to Q)
            double Qadj = Q - 3.0 * (double)N_ROWS * D_EPSLG2;
            double residue_sum = -D_LN2 * Qadj + D_C0 * K;
            const double invN = 1.0 / (double)N_ROWS;
            out[0] = (float)(LAMBDA_1 * 0.5 * M * invN);
            out[1] = (float)(LAMBDA_2 * residue_sum * invN);
            out[2] = (float)(K * invN);
            gs[0] = 0.0; gs[1] = 0.0; gs[2] = 0.0;
            __threadfence();
            g_ticket = 0u;
        }
    }
}

extern "C" void kernel_launch(void* const* d_in, const int* in_sizes, int n_in,
                              void* d_out, int out_size) {
    const float* inp = (const float*)d_in[0];
    const int*   tgt = (const int*)d_in[1];
    float*       out = (float*)d_out;
    (void)in_sizes; (void)n_in; (void)out_size;

    mrl_kernel<<<GRID, THREADS>>>(inp, tgt, out);
}